// round 4
// baseline (speedup 1.0000x reference)
#include <cuda_runtime.h>
#include <cuda_bf16.h>
#include <cstdint>

// Problem shapes
#define N_OBJ      512
#define N_CLS      151
#define N_REL      65536
#define REL_DIM    4096
#define N_RELCLS   51

#define OUT_OFF_DISTS 0
#define OUT_OFF_PREDS (N_OBJ * N_CLS)            // 77312
#define OUT_OFF_REL   (N_OBJ * N_CLS + N_OBJ)    // 77824

#define NMS_BLOCKS  150
#define GEMM_BLOCKS 512   // 65536 / 128

// -------- scratch (no allocation allowed) --------
__device__ float g_masked[N_OBJ * (N_CLS - 1)];  // keep*prob, [obj][class-1]

// -------- small PTX helpers --------
__device__ __forceinline__ uint32_t f2tf32(float x) {
    uint32_t y;
    asm volatile("cvt.rna.tf32.f32 %0, %1;" : "=r"(y) : "f"(x));
    return y;
}
__device__ __forceinline__ void cp_async16(uint32_t dst, const float* src) {
    asm volatile("cp.async.cg.shared.global [%0], [%1], 16;\n" :: "r"(dst), "l"(src));
}
__device__ __forceinline__ void cp_commit() {
    asm volatile("cp.async.commit_group;\n" ::);
}
__device__ __forceinline__ void cp_wait1() {
    asm volatile("cp.async.wait_group 1;\n" ::);
}
__device__ __forceinline__ void mma_tf32(float c[4], const uint32_t a[4], const uint32_t b[2]) {
    asm volatile(
        "mma.sync.aligned.m16n8k8.row.col.f32.tf32.tf32.f32 "
        "{%0,%1,%2,%3}, {%4,%5,%6,%7}, {%8,%9}, {%0,%1,%2,%3};\n"
        : "+f"(c[0]), "+f"(c[1]), "+f"(c[2]), "+f"(c[3])
        : "r"(a[0]), "r"(a[1]), "r"(a[2]), "r"(a[3]), "r"(b[0]), "r"(b[1]));
}

// -------- shared memory union --------
struct GemmSmem {            // tf32 GEMM, 128x64 tile, K-tile 32, 2 stages
    float A[2][128 * 32];    // 32 KB  (xor-swizzled on 16B granules)
    float B[2][52 * 32];     // 13 KB  (rows 0..50 = w, row 51 = zeros)
};
struct NmsSmem {
    float key[512];
    int   idx[512];
    float bx1[512], by1[512], bx2[512], by2[512], ar[512];
    int   act[512];
};
union SmemU { GemmSmem g; NmsSmem n; };

// swizzled float offset for an (row, k) element of a 32-wide fp32 tile
__device__ __forceinline__ int sw_off(int row, int k) {
    return row * 32 + ((((k >> 2) ^ (row & 7)) << 2) | (k & 3));
}

__global__ __launch_bounds__(512, 2)
void fused_kernel(const float* __restrict__ obj_logits,
                  const float* __restrict__ vr,
                  const float* __restrict__ boxes,   // [512][151][4]
                  const float* __restrict__ w,       // [51][4096]
                  const float* __restrict__ bias,    // [51]
                  float* __restrict__ out)
{
    __shared__ SmemU sm;
    const int tid  = threadIdx.x;
    const int lane = tid & 31;
    const int wid  = tid >> 5;

    if (blockIdx.x >= NMS_BLOCKS) {
        // ====================== GEMM block ======================
        const int g     = blockIdx.x - NMS_BLOCKS;
        const int mBase = g << 7;                  // 128 rows per CTA
        const int wm    = wid >> 2;                // 0..3 -> 32 rows
        const int wn    = wid & 3;                 // 0..3 -> 16 cols
        float* outRel   = out + OUT_OFF_REL;

        // zero pad row 51 of B (never overwritten by cp.async)
        if (tid < 32) {
            sm.g.B[0][51 * 32 + tid] = 0.f;
            sm.g.B[1][51 * 32 + tid] = 0.f;
        }

        const uint32_t aBase = (uint32_t)__cvta_generic_to_shared(sm.g.A);
        const uint32_t bBase = (uint32_t)__cvta_generic_to_shared(sm.g.B);

        float acc[2][2][4];
        #pragma unroll
        for (int i = 0; i < 2; i++)
            #pragma unroll
            for (int j = 0; j < 2; j++)
                #pragma unroll
                for (int r = 0; r < 4; r++) acc[i][j][r] = 0.f;

        auto loadTiles = [&](int kt, int buf) {
            const float* aSrc = vr + (size_t)mBase * REL_DIM + kt * 32;
            #pragma unroll
            for (int r = 0; r < 2; r++) {
                int idx = tid + (r << 9);          // 0..1023 : 128 rows x 8 float4
                int ml = idx >> 3, k4 = idx & 7;
                cp_async16(aBase + (uint32_t)(buf * 16384) +
                               (uint32_t)((ml * 32 + ((k4 ^ (ml & 7)) << 2)) * 4),
                           aSrc + ml * REL_DIM + (k4 << 2));
            }
            if (tid < 51 * 8) {
                int nl = tid >> 3, k4 = tid & 7;
                cp_async16(bBase + (uint32_t)(buf * 6656) +
                               (uint32_t)((nl * 32 + ((k4 ^ (nl & 7)) << 2)) * 4),
                           w + nl * REL_DIM + kt * 32 + (k4 << 2));
            }
        };

        loadTiles(0, 0);
        cp_commit();

        const int q  = lane >> 2;
        const int la = lane & 3;

        for (int kt = 0; kt < REL_DIM / 32; kt++) {
            const int cur = kt & 1;
            if (kt + 1 < REL_DIM / 32) loadTiles(kt + 1, cur ^ 1);
            cp_commit();
            cp_wait1();
            __syncthreads();

            const float* As = sm.g.A[cur];
            const float* Bs = sm.g.B[cur];

            #pragma unroll
            for (int k8 = 0; k8 < 4; k8++) {
                uint32_t afr[2][4], bfr[2][2];
                #pragma unroll
                for (int mt = 0; mt < 2; mt++) {
                    int r0 = wm * 32 + mt * 16 + q;
                    int r1 = r0 + 8;
                    afr[mt][0] = f2tf32(As[r0 * 32 + (((2 * k8)     ^ (r0 & 7)) << 2) + la]);
                    afr[mt][1] = f2tf32(As[r1 * 32 + (((2 * k8)     ^ (r1 & 7)) << 2) + la]);
                    afr[mt][2] = f2tf32(As[r0 * 32 + (((2 * k8 + 1) ^ (r0 & 7)) << 2) + la]);
                    afr[mt][3] = f2tf32(As[r1 * 32 + (((2 * k8 + 1) ^ (r1 & 7)) << 2) + la]);
                }
                #pragma unroll
                for (int nt = 0; nt < 2; nt++) {
                    int n = wn * 16 + nt * 8 + q;
                    if (n > 51) n = 51;            // clamp onto the zero row
                    bfr[nt][0] = f2tf32(Bs[n * 32 + (((2 * k8)     ^ (n & 7)) << 2) + la]);
                    bfr[nt][1] = f2tf32(Bs[n * 32 + (((2 * k8 + 1) ^ (n & 7)) << 2) + la]);
                }
                #pragma unroll
                for (int mt = 0; mt < 2; mt++)
                    #pragma unroll
                    for (int nt = 0; nt < 2; nt++) {
                        if (wn == 3 && nt == 1) continue;  // cols 56..63 all dead
                        mma_tf32(acc[mt][nt], afr[mt], bfr[nt]);
                    }
            }
            __syncthreads();
        }

        // epilogue: C frag (c0:(q,2la) c1:(q,2la+1) c2:(q+8,2la) c3:(q+8,2la+1))
        #pragma unroll
        for (int mt = 0; mt < 2; mt++)
            #pragma unroll
            for (int nt = 0; nt < 2; nt++) {
                if (wn == 3 && nt == 1) continue;
                int row = mBase + wm * 32 + mt * 16 + q;
                int col = wn * 16 + nt * 8 + 2 * la;
                if (col < N_RELCLS) {
                    float bc = bias[col];
                    outRel[row * N_RELCLS + col]       = acc[mt][nt][0] + bc;
                    outRel[(row + 8) * N_RELCLS + col] = acc[mt][nt][2] + bc;
                }
                if (col + 1 < N_RELCLS) {
                    float bc = bias[col + 1];
                    outRel[row * N_RELCLS + col + 1]       = acc[mt][nt][1] + bc;
                    outRel[(row + 8) * N_RELCLS + col + 1] = acc[mt][nt][3] + bc;
                }
            }
    } else {
        // ====================== NMS block (one class) ======================
        const int cls = blockIdx.x + 1;   // classes 1..150

        // softmax prob[o][cls]; warp-per-object, deterministic reduction order
        for (int o = wid; o < N_OBJ; o += 16) {
            const float* lg = obj_logits + o * N_CLS;
            float mx = -1e30f;
            for (int k = lane; k < N_CLS; k += 32) mx = fmaxf(mx, lg[k]);
            #pragma unroll
            for (int off = 16; off; off >>= 1)
                mx = fmaxf(mx, __shfl_xor_sync(0xFFFFFFFFu, mx, off));
            float s = 0.f;
            for (int k = lane; k < N_CLS; k += 32) s += __expf(lg[k] - mx);
            #pragma unroll
            for (int off = 16; off; off >>= 1)
                s += __shfl_xor_sync(0xFFFFFFFFu, s, off);
            if (lane == 0) {
                sm.n.key[o] = __expf(lg[cls] - mx) / s;
                sm.n.idx[o] = o;
            }
        }
        __syncthreads();

        // bitonic sort, descending by prob (key, idx) — 512 elems, 512 threads
        for (int k = 2; k <= 512; k <<= 1) {
            for (int j = k >> 1; j > 0; j >>= 1) {
                int ixj = tid ^ j;
                if (ixj > tid) {
                    bool desc = ((tid & k) == 0);
                    float a = sm.n.key[tid], b2 = sm.n.key[ixj];
                    if (desc ? (a < b2) : (a > b2)) {
                        sm.n.key[tid] = b2; sm.n.key[ixj] = a;
                        int t = sm.n.idx[tid]; sm.n.idx[tid] = sm.n.idx[ixj]; sm.n.idx[ixj] = t;
                    }
                }
                __syncthreads();
            }
        }

        const int src = sm.n.idx[tid];
        const float* bx = boxes + ((size_t)src * N_CLS + cls) * 4;
        float X1 = bx[0], Y1 = bx[1], X2 = bx[2], Y2 = bx[3];
        float AR = (X2 - X1 + 1.f) * (Y2 - Y1 + 1.f);
        sm.n.bx1[tid] = X1; sm.n.by1[tid] = Y1;
        sm.n.bx2[tid] = X2; sm.n.by2[tid] = Y2;
        sm.n.ar[tid]  = AR;
        sm.n.act[tid] = 1;

        // sequential greedy suppression; final act[i] == keep_sorted[i]
        for (int i = 0; i < N_OBJ - 1; i++) {
            __syncthreads();
            if (tid > i && sm.n.act[tid] && sm.n.act[i]) {
                float xx1 = fmaxf(sm.n.bx1[i], X1);
                float yy1 = fmaxf(sm.n.by1[i], Y1);
                float xx2 = fminf(sm.n.bx2[i], X2);
                float yy2 = fminf(sm.n.by2[i], Y2);
                float ww = fmaxf(xx2 - xx1 + 1.f, 0.f);
                float hh = fmaxf(yy2 - yy1 + 1.f, 0.f);
                float inter = ww * hh;
                float iou = inter / (sm.n.ar[i] + AR - inter);
                if (iou > 0.3f) sm.n.act[tid] = 0;
            }
        }
        __syncthreads();
        g_masked[src * (N_CLS - 1) + (cls - 1)] = sm.n.act[tid] ? sm.n.key[tid] : 0.f;
    }
}

// obj_preds = argmax over masked probs (first max), +1
__global__ void preds_kernel(float* __restrict__ out) {
    int o = threadIdx.x;
    const float* row = g_masked + o * (N_CLS - 1);
    float best = row[0];
    int bi = 0;
    for (int j = 1; j < N_CLS - 1; j++) {
        float v = row[j];
        if (v > best) { best = v; bi = j; }
    }
    out[OUT_OFF_PREDS + o] = (float)(bi + 1);
}

extern "C" void kernel_launch(void* const* d_in, const int* in_sizes, int n_in,
                              void* d_out, int out_size) {
    const float* obj_logits = (const float*)d_in[0];
    const float* vr         = (const float*)d_in[1];
    const float* boxes      = (const float*)d_in[2];
    const float* w          = (const float*)d_in[3];
    const float* b          = (const float*)d_in[4];
    float* out = (float*)d_out;

    // obj_dists2 = obj_logits (exact copy)
    cudaMemcpyAsync(out + OUT_OFF_DISTS, obj_logits,
                    (size_t)N_OBJ * N_CLS * sizeof(float),
                    cudaMemcpyDeviceToDevice, 0);

    // NMS blocks first (wave 1) so they overlap the GEMM's memory time
    fused_kernel<<<NMS_BLOCKS + GEMM_BLOCKS, 512>>>(obj_logits, vr, boxes, w, b, out);
    preds_kernel<<<1, N_OBJ>>>(out);
}